// round 14
// baseline (speedup 1.0000x reference)
#include <cuda_runtime.h>
#include <cuda_fp16.h>
#include <math.h>
#include <stdint.h>

#define BB 8
#define NN 4096
#define DIM 512
#define HEADS 8
#define DHEAD 64
#define DINNER 512
#define BH (BB*HEADS)       // 64

// ---------------- scratch (static device globals) ----------------
__device__ __half g_q[(size_t)BB*DINNER*NN];  // [b][hd][n] fp16
__device__ __half g_k[(size_t)BB*DINNER*NN];  // [b][hd][n] fp16
__device__ __half g_v[(size_t)BB*NN*DINNER];  // [b][n][c]  fp16
__device__ __half g_x[(size_t)BB*NN*DIM];     // normalized x, [m][k] fp16
__device__ __half g_w[1536*DIM];              // w_qkv^T, [c][k] fp16
__device__ __half g_aw[(size_t)BB*DIM*DINNER];// attn-folded w_out^T, [b][j][c] fp16
__device__ float g_invnq[BH*DHEAD];
__device__ float g_invnk[BH*DHEAD];
__device__ float g_gpart[BH*8*DHEAD*DHEAD];
__device__ float g_attn[BH*DHEAD*DHEAD];

// ---------------- helpers ----------------
__device__ __forceinline__ uint32_t smem_u32(const void* p) {
    uint32_t a;
    asm("{ .reg .u64 t; cvta.to.shared.u64 t, %1; cvt.u32.u64 %0, t; }" : "=r"(a) : "l"(p));
    return a;
}
// swizzle for 128B rows (64 fp16)
__device__ __forceinline__ uint32_t sw128(uint32_t o) { return o ^ ((o >> 3) & 0x70); }

__device__ __forceinline__ void ldsm4(uint32_t* r, uint32_t addr) {
    asm volatile("ldmatrix.sync.aligned.m8n8.x4.shared.b16 {%0,%1,%2,%3}, [%4];"
                 : "=r"(r[0]), "=r"(r[1]), "=r"(r[2]), "=r"(r[3]) : "r"(addr));
}
__device__ __forceinline__ void mma16816(float* d, const uint32_t* a, const uint32_t* b) {
    asm volatile("mma.sync.aligned.m16n8k16.row.col.f32.f16.f16.f32 "
                 "{%0,%1,%2,%3}, {%4,%5,%6,%7}, {%8,%9}, {%0,%1,%2,%3};"
                 : "+f"(d[0]), "+f"(d[1]), "+f"(d[2]), "+f"(d[3])
                 : "r"(a[0]), "r"(a[1]), "r"(a[2]), "r"(a[3]), "r"(b[0]), "r"(b[1]));
}
__device__ __forceinline__ void cpasync16(uint32_t dst, const void* src) {
    asm volatile("cp.async.cg.shared.global [%0], [%1], 16;" :: "r"(dst), "l"(src) : "memory");
}
#define CP_COMMIT() asm volatile("cp.async.commit_group;" ::: "memory")
#define CP_WAIT1()  asm volatile("cp.async.wait_group 1;" ::: "memory")
#define CP_WAIT0()  asm volatile("cp.async.wait_group 0;" ::: "memory")

__device__ __forceinline__ uint32_t packh2(float a, float b) {
    __half2 h = __floats2half2_rn(a, b);
    return *reinterpret_cast<uint32_t*>(&h);
}

// ======= 3-stage pipelined fp16 MMA mainloop, K-chunk = 64 =======
// warp grid 2(m) x 4(n); warp tile (AM*16) x (BN*8).
// Rows are 128B (64 fp16) in smem, SW128-swizzled; 4 ks-steps per chunk.
template<int ROWS, int AM, int BN, int NCH>
__device__ __forceinline__ void mma_pipe(char* smem,
        const __half* __restrict__ A, const __half* __restrict__ B,
        int ldA, int ldB, float (*acc)[BN][4]) {
    const int tid = threadIdx.x;
    const int wid = tid >> 5, lane = tid & 31;
    const int wm = wid >> 2, wn = wid & 3;
    const int g = lane >> 3, lr = lane & 7;
    const uint32_t sb = smem_u32(smem);
    constexpr int TILE = ROWS * 128;       // bytes per tile (64 fp16/row)
    constexpr int STAGE = 2 * TILE;
    constexpr int LIT = (ROWS * 8) / 256;  // 16B-chunks per thread per tile
    constexpr int NB = (BN + 1) / 2;
    const int a_row = wm * (AM * 16) + lr + (g & 1) * 8;
    const int a_cb = (g >> 1);
    const int b_row = wn * (BN * 8) + lr + (g >> 1) * 8;
    const int b_cb = (g & 1);

    auto issue = [&](int ch, int st) {
        uint32_t base = sb + st * STAGE;
        #pragma unroll
        for (int i = 0; i < LIT; i++) {
            int idx = tid + 256 * i;
            int row = idx >> 3, c = idx & 7;
            uint32_t so = sw128((uint32_t)(row * 128 + c * 16));
            int col = ch * 64 + c * 8;
            cpasync16(base + so,        A + (size_t)row * ldA + col);
            cpasync16(base + TILE + so, B + (size_t)row * ldB + col);
        }
    };

    issue(0, 0); CP_COMMIT();
    issue(1, 1); CP_COMMIT();
    for (int ch = 0; ch < NCH; ch++) {
        if (ch < NCH - 1) { CP_WAIT1(); } else { CP_WAIT0(); }
        __syncthreads();
        if (ch + 2 < NCH) { issue(ch + 2, (ch + 2) % 3); CP_COMMIT(); }
        uint32_t stb = sb + (ch % 3) * STAGE;
        #pragma unroll
        for (int ks = 0; ks < 4; ks++) {
            uint32_t ah[AM][4], bfr[NB][4];
            #pragma unroll
            for (int mi = 0; mi < AM; mi++) {
                uint32_t off = sw128((uint32_t)((a_row + mi * 16) * 128 + (a_cb + ks * 2) * 16));
                ldsm4(ah[mi], stb + off);
            }
            #pragma unroll
            for (int t = 0; t < NB; t++) {
                uint32_t off = sw128((uint32_t)((b_row + t * 16) * 128 + (b_cb + ks * 2) * 16));
                ldsm4(bfr[t], stb + TILE + off);
            }
            #pragma unroll
            for (int mi = 0; mi < AM; mi++)
                #pragma unroll
                for (int nj = 0; nj < BN; nj++)
                    mma16816(acc[mi][nj], ah[mi], &bfr[nj >> 1][(nj & 1) * 2]);
        }
    }
    __syncthreads();
}

#define SMEM_GEMM (3 * 2 * 128 * 128)  // 98304 (also covers 136x128 fp16 staging = 34816)
#define SMEM_SIM  (3 * 2 * 64 * 128)   // 49152

// -------- K0a: fused RMSNorm + fp16 round of activations ----
__global__ void k_prepA(const float* __restrict__ x, const float* __restrict__ gamma) {
    const int row = blockIdx.x;
    const int tid = threadIdx.x;
    const float4 v = ((const float4*)(x + (size_t)row * DIM))[tid];
    float s = v.x * v.x + v.y * v.y + v.z * v.z + v.w * v.w;
    #pragma unroll
    for (int o = 16; o; o >>= 1) s += __shfl_xor_sync(0xffffffffu, s, o);
    __shared__ float ws[4];
    __shared__ float rs_sh;
    if ((tid & 31) == 0) ws[tid >> 5] = s;
    __syncthreads();
    if (tid == 0)
        rs_sh = 22.62741699796952f / fmaxf(sqrtf(ws[0] + ws[1] + ws[2] + ws[3]), 1e-12f);
    __syncthreads();
    const float rs = rs_sh;
    const float4 g = ((const float4*)gamma)[tid];
    uint2 p;
    p.x = packh2(v.x * rs * g.x, v.y * rs * g.y);
    p.y = packh2(v.z * rs * g.z, v.w * rs * g.w);
    ((uint2*)(g_x + (size_t)row * DIM))[tid] = p;
}

// -------- K0b: transpose w_qkv -> [c][k] fp16 --------
__global__ void k_prepW(const float* __restrict__ w) {
    __shared__ float t[32][33];
    const int c0 = blockIdx.x * 32, k0 = blockIdx.y * 32;
    const int tx = threadIdx.x, ty = threadIdx.y;
    #pragma unroll
    for (int i = 0; i < 4; i++)
        t[ty + 8 * i][tx] = w[(size_t)(k0 + ty + 8 * i) * 1536 + c0 + tx];
    __syncthreads();
    #pragma unroll
    for (int i = 0; i < 4; i++)
        g_w[(size_t)(c0 + ty + 8 * i) * 512 + k0 + tx] = __float2half_rn(t[tx][ty + 8 * i]);
}

// -------- QKV GEMM: D[m][c] = xn @ w_qkv (fp16 1-term) --------
// Epilogue stages the tile in smem ([c][n] for q/k, [n][c] for v) and writes
// fully coalesced 16B rows instead of scattered 2B stores.
__global__ __launch_bounds__(256, 2) void k_qkv_mma() {
    extern __shared__ char smem[];
    const int m0 = blockIdx.x * 128;
    const int c0 = blockIdx.y * 128;
    const int which = c0 >> 9;          // 0:q 1:k 2:v (tile never straddles)
    float acc[4][4][4];
    #pragma unroll
    for (int i = 0; i < 4; i++)
        #pragma unroll
        for (int j = 0; j < 4; j++)
            #pragma unroll
            for (int r = 0; r < 4; r++) acc[i][j][r] = 0.f;

    mma_pipe<128, 4, 4, 8>(smem,
                 g_x + (size_t)m0 * 512, g_w + (size_t)c0 * 512, 512, 512, acc);

    const int tid = threadIdx.x;
    const int wid = tid >> 5, lane = tid & 31;
    const int wm = wid >> 2, wn = wid & 3;
    const int b = m0 >> 12;

    // stage into smem (rows padded to 136 halves = 272B, 16B-aligned stride)
    __half* sm = (__half*)smem;
    const int SMS = 136;
    if (which < 2) {
        // smem[c][n]
        #pragma unroll
        for (int mi = 0; mi < 4; mi++)
            #pragma unroll
            for (int nj = 0; nj < 4; nj++) {
                int cl = wn * 32 + 2 * (lane & 3) + nj * 8;
                #pragma unroll
                for (int h = 0; h < 2; h++) {
                    int nl = wm * 64 + (lane >> 2) + mi * 16 + h * 8;
                    sm[cl * SMS + nl]       = __float2half_rn(acc[mi][nj][h * 2]);
                    sm[(cl + 1) * SMS + nl] = __float2half_rn(acc[mi][nj][h * 2 + 1]);
                }
            }
    } else {
        // smem[n][c], pack adjacent c-pair as u32
        #pragma unroll
        for (int mi = 0; mi < 4; mi++)
            #pragma unroll
            for (int nj = 0; nj < 4; nj++) {
                int cl = wn * 32 + 2 * (lane & 3) + nj * 8;
                #pragma unroll
                for (int h = 0; h < 2; h++) {
                    int nl = wm * 64 + (lane >> 2) + mi * 16 + h * 8;
                    *(uint32_t*)&sm[nl * SMS + cl] =
                        packh2(acc[mi][nj][h * 2], acc[mi][nj][h * 2 + 1]);
                }
            }
    }
    __syncthreads();
    {
        const int r = tid >> 1, half = (tid & 1) * 64;
        const uint4* src = (const uint4*)(sm + r * SMS + half);
        __half* dst;
        if (which < 2)
            dst = (which ? g_k : g_q) + (size_t)b * DINNER * NN +
                  (size_t)((c0 & 511) + r) * NN + (m0 & 4095) + half;
        else
            dst = g_v + ((size_t)b * NN + (m0 & 4095) + r) * DINNER + (c0 & 511) + half;
        uint4* d4 = (uint4*)dst;
        #pragma unroll
        for (int i = 0; i < 8; i++) d4[i] = src[i];
    }
}

// -------- K3: 1/||row|| over n for q and k --------
__global__ void k_rownorm() {
    int row = blockIdx.x;              // 0..8191 (q rows then k rows)
    int r = row & 4095;
    const __half* p = ((row < 4096) ? g_q : g_k) + (size_t)r * NN;
    int tid = threadIdx.x;
    float s = 0.f;
    #pragma unroll
    for (int t = 0; t < 2; t++) {
        int idx = (tid + 256 * t) * 8;
        uint4 vh = *(const uint4*)(p + idx);
        const uint32_t* hw = &vh.x;
        #pragma unroll
        for (int i = 0; i < 4; i++) {
            float2 h2 = __half22float2(*(const __half2*)&hw[i]);
            s += h2.x * h2.x + h2.y * h2.y;
        }
    }
    #pragma unroll
    for (int o = 16; o; o >>= 1) s += __shfl_xor_sync(0xffffffffu, s, o);
    __shared__ float ws[8];
    if ((tid & 31) == 0) ws[tid >> 5] = s;
    __syncthreads();
    if (tid == 0) {
        float t = 0.f;
        #pragma unroll
        for (int i = 0; i < 8; i++) t += ws[i];
        float inv = 1.0f / fmaxf(sqrtf(t), 1e-12f);
        if (row < 4096) g_invnq[row] = inv; else g_invnk[row & 4095] = inv;
    }
}

// -------- K4: sim partials via HMMA over a 512-wide n slice ----
__global__ __launch_bounds__(256) void k_sim_mma() {
    extern __shared__ char smem[];
    const int bh = blockIdx.x;   // 64
    const int sp = blockIdx.y;   // 8 splits of n
    float acc[2][2][4];
    #pragma unroll
    for (int i = 0; i < 2; i++)
        #pragma unroll
        for (int j = 0; j < 2; j++)
            #pragma unroll
            for (int r = 0; r < 4; r++) acc[i][j][r] = 0.f;

    const size_t base = (size_t)bh * DHEAD * NN + sp * 512;
    mma_pipe<64, 2, 2, 8>(smem, g_q + base, g_k + base, NN, NN, acc);

    const int tid = threadIdx.x;
    const int wid = tid >> 5, lane = tid & 31;
    const int wm = wid >> 2, wn = wid & 3;
    float* gp = g_gpart + ((size_t)bh * 8 + sp) * 4096;
    #pragma unroll
    for (int mi = 0; mi < 2; mi++)
        #pragma unroll
        for (int h = 0; h < 2; h++) {
            int d = wm * 32 + mi * 16 + (lane >> 2) + h * 8;
            #pragma unroll
            for (int nj = 0; nj < 2; nj++) {
                int e = wn * 16 + nj * 8 + 2 * (lane & 3);
                *(float2*)(gp + d * 64 + e) =
                    make_float2(acc[mi][nj][h * 2], acc[mi][nj][h * 2 + 1]);
            }
        }
}

// -------- K5: reduce + scale + softmax --------
__global__ void k_softmax(const float* __restrict__ temperature) {
    const int bh = blockIdx.x;
    const int d = threadIdx.x;
    const int hh = bh & 7;
    const float sc = 8.0f * expf(temperature[hh]) * g_invnq[bh * 64 + d];
    const float* gp = g_gpart + (size_t)bh * 8 * 4096;
    float vals[64];
    float mx = -1e30f;
    #pragma unroll 4
    for (int e = 0; e < 64; e++) {
        float s = 0.f;
        #pragma unroll
        for (int sp = 0; sp < 8; sp++) s += gp[sp * 4096 + d * 64 + e];
        s *= sc * g_invnk[bh * 64 + e];
        vals[e] = s;
        mx = fmaxf(mx, s);
    }
    float sum = 0.f;
    #pragma unroll 4
    for (int e = 0; e < 64; e++) { vals[e] = expf(vals[e] - mx); sum += vals[e]; }
    const float inv = 1.0f / sum;
    #pragma unroll 4
    for (int e = 0; e < 64; e++)
        g_attn[(size_t)bh * 4096 + d * 64 + e] = vals[e] * inv;
}

// -------- K6: fold attn into w_out, write transposed fp16 [b][j][c] --------
__global__ __launch_bounds__(256) void k_attnw(const float* __restrict__ w_out) {
    const int bh = blockIdx.x;
    const int jt = blockIdx.y;
    const int b = bh >> 3, hh = bh & 7;
    __shared__ float As[64][64];
    const int tid = threadIdx.x;
    #pragma unroll
    for (int t = 0; t < 16; t++) {
        int idx = tid + 256 * t;
        As[idx >> 6][idx & 63] = g_attn[(size_t)bh * 4096 + idx];
    }
    __syncthreads();
    const int j = jt * 128 + (tid & 127);
    const int e0 = (tid >> 7) * 32;
    float acc[32];
    #pragma unroll
    for (int i = 0; i < 32; i++) acc[i] = 0.f;
    for (int d = 0; d < 64; d++) {
        float w = w_out[(hh * 64 + d) * DIM + j];
        #pragma unroll
        for (int i = 0; i < 32; i++) acc[i] += As[d][e0 + i] * w;
    }
    size_t base = ((size_t)b * 512 + j) * 512 + hh * 64 + e0;
    #pragma unroll
    for (int i = 0; i < 32; i++)
        g_aw[base + i] = __float2half_rn(acc[i]);
}

// -------- final GEMM: out[b][n][j] = sum_c V[b][n][c] * aw[b][j][c] --------
__global__ __launch_bounds__(256, 2) void k_final_mma(float* __restrict__ out) {
    extern __shared__ char smem[];
    const int m0 = blockIdx.x * 128;   // n
    const int j0 = blockIdx.y * 128;   // j
    const int b = blockIdx.z;
    float acc[4][4][4];
    #pragma unroll
    for (int i = 0; i < 4; i++)
        #pragma unroll
        for (int j = 0; j < 4; j++)
            #pragma unroll
            for (int r = 0; r < 4; r++) acc[i][j][r] = 0.f;

    mma_pipe<128, 4, 4, 8>(smem,
                 g_v + ((size_t)b * NN + m0) * 512,
                 g_aw + ((size_t)b * 512 + j0) * 512, 512, 512, acc);

    const int tid = threadIdx.x;
    const int wid = tid >> 5, lane = tid & 31;
    const int wm = wid >> 2, wn = wid & 3;
    const int nbase = m0 + wm * 64 + (lane >> 2);
    const int jbase = j0 + wn * 32 + 2 * (lane & 3);
    #pragma unroll
    for (int mi = 0; mi < 4; mi++)
        #pragma unroll
        for (int h = 0; h < 2; h++) {
            int n = nbase + mi * 16 + h * 8;
            float* orow = out + ((size_t)b * NN + n) * DIM + jbase;
            #pragma unroll
            for (int nj = 0; nj < 4; nj++) {
                float2 v = make_float2(acc[mi][nj][h * 2], acc[mi][nj][h * 2 + 1]);
                *(float2*)(orow + nj * 8) = v;
            }
        }
}

// -------- launch --------
extern "C" void kernel_launch(void* const* d_in, const int* in_sizes, int n_in,
                              void* d_out, int out_size) {
    const float* x           = (const float*)d_in[0];
    const float* gamma       = (const float*)d_in[1];
    const float* w_qkv       = (const float*)d_in[2];
    const float* temperature = (const float*)d_in[3];
    const float* w_out       = (const float*)d_in[4];
    float* out = (float*)d_out;

    static int attr_done = 0;
    if (!attr_done) {
        cudaFuncSetAttribute(k_qkv_mma, cudaFuncAttributeMaxDynamicSharedMemorySize, SMEM_GEMM);
        cudaFuncSetAttribute(k_final_mma, cudaFuncAttributeMaxDynamicSharedMemorySize, SMEM_GEMM);
        cudaFuncSetAttribute(k_sim_mma, cudaFuncAttributeMaxDynamicSharedMemorySize, SMEM_SIM);
        attr_done = 1;
    }

    k_prepA    <<<BB * NN, 128>>>(x, gamma);
    k_prepW    <<<dim3(48, 16), dim3(32, 8)>>>(w_qkv);
    k_qkv_mma  <<<dim3(256, 12), 256, SMEM_GEMM>>>();
    k_rownorm  <<<2 * BH * DHEAD, 256>>>();
    k_sim_mma  <<<dim3(BH, 8), 256, SMEM_SIM>>>();
    k_softmax  <<<BH, 64>>>(temperature);
    k_attnw    <<<dim3(BH, 4), 256>>>(w_out);
    k_final_mma<<<dim3(32, 4, BB), 256, SMEM_GEMM>>>(out);
}

// round 15
// speedup vs baseline: 1.0435x; 1.0435x over previous
#include <cuda_runtime.h>
#include <cuda_fp16.h>
#include <math.h>
#include <stdint.h>

#define BB 8
#define NN 4096
#define DIM 512
#define HEADS 8
#define DHEAD 64
#define DINNER 512
#define BH (BB*HEADS)       // 64

// ---------------- scratch (static device globals) ----------------
__device__ __half g_q[(size_t)BB*DINNER*NN];  // [b][hd][n] fp16
__device__ __half g_k[(size_t)BB*DINNER*NN];  // [b][hd][n] fp16
__device__ __half g_v[(size_t)BB*NN*DINNER];  // [b][n][c]  fp16
__device__ __half g_x[(size_t)BB*NN*DIM];     // normalized x, [m][k] fp16
__device__ __half g_w[1536*DIM];              // w_qkv^T, [c][k] fp16
__device__ __half g_aw[(size_t)BB*DIM*DINNER];// attn-folded w_out^T, [b][j][c] fp16
__device__ float g_ssq_q[BB*DINNER];          // per-row sum of squares (fused rownorm)
__device__ float g_ssq_k[BB*DINNER];
__device__ float g_gpart[BH*8*DHEAD*DHEAD];
__device__ float g_attn[BH*DHEAD*DHEAD];

// ---------------- helpers ----------------
__device__ __forceinline__ uint32_t smem_u32(const void* p) {
    uint32_t a;
    asm("{ .reg .u64 t; cvta.to.shared.u64 t, %1; cvt.u32.u64 %0, t; }" : "=r"(a) : "l"(p));
    return a;
}
// swizzle for 128B rows (64 fp16)
__device__ __forceinline__ uint32_t sw128(uint32_t o) { return o ^ ((o >> 3) & 0x70); }

__device__ __forceinline__ void ldsm4(uint32_t* r, uint32_t addr) {
    asm volatile("ldmatrix.sync.aligned.m8n8.x4.shared.b16 {%0,%1,%2,%3}, [%4];"
                 : "=r"(r[0]), "=r"(r[1]), "=r"(r[2]), "=r"(r[3]) : "r"(addr));
}
__device__ __forceinline__ void mma16816(float* d, const uint32_t* a, const uint32_t* b) {
    asm volatile("mma.sync.aligned.m16n8k16.row.col.f32.f16.f16.f32 "
                 "{%0,%1,%2,%3}, {%4,%5,%6,%7}, {%8,%9}, {%0,%1,%2,%3};"
                 : "+f"(d[0]), "+f"(d[1]), "+f"(d[2]), "+f"(d[3])
                 : "r"(a[0]), "r"(a[1]), "r"(a[2]), "r"(a[3]), "r"(b[0]), "r"(b[1]));
}
__device__ __forceinline__ void cpasync16(uint32_t dst, const void* src) {
    asm volatile("cp.async.cg.shared.global [%0], [%1], 16;" :: "r"(dst), "l"(src) : "memory");
}
#define CP_COMMIT() asm volatile("cp.async.commit_group;" ::: "memory")
#define CP_WAIT1()  asm volatile("cp.async.wait_group 1;" ::: "memory")
#define CP_WAIT0()  asm volatile("cp.async.wait_group 0;" ::: "memory")

__device__ __forceinline__ unsigned short packh(float a) {
    __half h = __float2half_rn(a);
    return *reinterpret_cast<unsigned short*>(&h);
}
__device__ __forceinline__ uint32_t packh2(float a, float b) {
    __half2 h = __floats2half2_rn(a, b);
    return *reinterpret_cast<uint32_t*>(&h);
}

// ======= 3-stage pipelined fp16 MMA mainloop, K-chunk = 64 =======
// warp grid 2(m) x 4(n); warp tile (AM*16) x (BN*8).
// Rows are 128B (64 fp16) in smem, SW128-swizzled; 4 ks-steps per chunk.
template<int ROWS, int AM, int BN, int NCH>
__device__ __forceinline__ void mma_pipe(char* smem,
        const __half* __restrict__ A, const __half* __restrict__ B,
        int ldA, int ldB, float (*acc)[BN][4]) {
    const int tid = threadIdx.x;
    const int wid = tid >> 5, lane = tid & 31;
    const int wm = wid >> 2, wn = wid & 3;
    const int g = lane >> 3, lr = lane & 7;
    const uint32_t sb = smem_u32(smem);
    constexpr int TILE = ROWS * 128;       // bytes per tile (64 fp16/row)
    constexpr int STAGE = 2 * TILE;
    constexpr int LIT = (ROWS * 8) / 256;  // 16B-chunks per thread per tile
    constexpr int NB = (BN + 1) / 2;
    const int a_row = wm * (AM * 16) + lr + (g & 1) * 8;
    const int a_cb = (g >> 1);
    const int b_row = wn * (BN * 8) + lr + (g >> 1) * 8;
    const int b_cb = (g & 1);

    auto issue = [&](int ch, int st) {
        uint32_t base = sb + st * STAGE;
        #pragma unroll
        for (int i = 0; i < LIT; i++) {
            int idx = tid + 256 * i;
            int row = idx >> 3, c = idx & 7;
            uint32_t so = sw128((uint32_t)(row * 128 + c * 16));
            int col = ch * 64 + c * 8;
            cpasync16(base + so,        A + (size_t)row * ldA + col);
            cpasync16(base + TILE + so, B + (size_t)row * ldB + col);
        }
    };

    issue(0, 0); CP_COMMIT();
    issue(1, 1); CP_COMMIT();
    for (int ch = 0; ch < NCH; ch++) {
        if (ch < NCH - 1) { CP_WAIT1(); } else { CP_WAIT0(); }
        __syncthreads();
        if (ch + 2 < NCH) { issue(ch + 2, (ch + 2) % 3); CP_COMMIT(); }
        uint32_t stb = sb + (ch % 3) * STAGE;
        #pragma unroll
        for (int ks = 0; ks < 4; ks++) {
            uint32_t ah[AM][4], bfr[NB][4];
            #pragma unroll
            for (int mi = 0; mi < AM; mi++) {
                uint32_t off = sw128((uint32_t)((a_row + mi * 16) * 128 + (a_cb + ks * 2) * 16));
                ldsm4(ah[mi], stb + off);
            }
            #pragma unroll
            for (int t = 0; t < NB; t++) {
                uint32_t off = sw128((uint32_t)((b_row + t * 16) * 128 + (b_cb + ks * 2) * 16));
                ldsm4(bfr[t], stb + TILE + off);
            }
            #pragma unroll
            for (int mi = 0; mi < AM; mi++)
                #pragma unroll
                for (int nj = 0; nj < BN; nj++)
                    mma16816(acc[mi][nj], ah[mi], &bfr[nj >> 1][(nj & 1) * 2]);
        }
    }
    __syncthreads();
}

#define SMEM_GEMM (3 * 2 * 128 * 128)  // 98304
#define SMEM_SIM  (3 * 2 * 64 * 128)   // 49152

// -------- K00: zero the fused-rownorm accumulators (graph-replay safe) ----
__global__ void k_zero() {
    int i = blockIdx.x * 256 + threadIdx.x;
    g_ssq_q[i] = 0.f;
    g_ssq_k[i] = 0.f;
}

// -------- K0a: fused RMSNorm + fp16 round of activations ----
__global__ void k_prepA(const float* __restrict__ x, const float* __restrict__ gamma) {
    const int row = blockIdx.x;
    const int tid = threadIdx.x;
    const float4 v = ((const float4*)(x + (size_t)row * DIM))[tid];
    float s = v.x * v.x + v.y * v.y + v.z * v.z + v.w * v.w;
    #pragma unroll
    for (int o = 16; o; o >>= 1) s += __shfl_xor_sync(0xffffffffu, s, o);
    __shared__ float ws[4];
    __shared__ float rs_sh;
    if ((tid & 31) == 0) ws[tid >> 5] = s;
    __syncthreads();
    if (tid == 0)
        rs_sh = 22.62741699796952f / fmaxf(sqrtf(ws[0] + ws[1] + ws[2] + ws[3]), 1e-12f);
    __syncthreads();
    const float rs = rs_sh;
    const float4 g = ((const float4*)gamma)[tid];
    uint2 p;
    p.x = packh2(v.x * rs * g.x, v.y * rs * g.y);
    p.y = packh2(v.z * rs * g.z, v.w * rs * g.w);
    ((uint2*)(g_x + (size_t)row * DIM))[tid] = p;
}

// -------- K0b: transpose w_qkv -> [c][k] fp16 --------
__global__ void k_prepW(const float* __restrict__ w) {
    __shared__ float t[32][33];
    const int c0 = blockIdx.x * 32, k0 = blockIdx.y * 32;
    const int tx = threadIdx.x, ty = threadIdx.y;
    #pragma unroll
    for (int i = 0; i < 4; i++)
        t[ty + 8 * i][tx] = w[(size_t)(k0 + ty + 8 * i) * 1536 + c0 + tx];
    __syncthreads();
    #pragma unroll
    for (int i = 0; i < 4; i++)
        g_w[(size_t)(c0 + ty + 8 * i) * 512 + k0 + tx] = __float2half_rn(t[tx][ty + 8 * i]);
}

// -------- QKV GEMM: D[m][c] = xn @ w_qkv (fp16 1-term) --------
// q/k epilogue also accumulates per-row sum-of-squares (fused rownorm).
__global__ __launch_bounds__(256, 2) void k_qkv_mma() {
    extern __shared__ char smem[];
    const int m0 = blockIdx.x * 128;
    const int c0 = blockIdx.y * 128;
    const int which = c0 >> 9;          // 0:q 1:k 2:v (tile never straddles)
    float acc[4][4][4];
    #pragma unroll
    for (int i = 0; i < 4; i++)
        #pragma unroll
        for (int j = 0; j < 4; j++)
            #pragma unroll
            for (int r = 0; r < 4; r++) acc[i][j][r] = 0.f;

    mma_pipe<128, 4, 4, 8>(smem,
                 g_x + (size_t)m0 * 512, g_w + (size_t)c0 * 512, 512, 512, acc);

    const int tid = threadIdx.x;
    const int wid = tid >> 5, lane = tid & 31;
    const int wm = wid >> 2, wn = wid & 3;
    const int b = m0 >> 12;
    const int nbase = (m0 & 4095) + wm * 64 + (lane >> 2);
    const int cloc = wn * 32 + 2 * (lane & 3);
    const int cbase = (c0 & 511) + cloc;

    if (which < 2) {
        __half* dst = (which ? g_k : g_q) + (size_t)b * DINNER * NN;
        float ss[4][2];
        #pragma unroll
        for (int nj = 0; nj < 4; nj++) { ss[nj][0] = 0.f; ss[nj][1] = 0.f; }
        #pragma unroll
        for (int mi = 0; mi < 4; mi++)
            #pragma unroll
            for (int nj = 0; nj < 4; nj++) {
                int c = cbase + nj * 8;
                #pragma unroll
                for (int h = 0; h < 2; h++) {
                    int n = nbase + mi * 16 + h * 8;
                    float v0 = acc[mi][nj][h * 2], v1 = acc[mi][nj][h * 2 + 1];
                    ss[nj][0] += v0 * v0;
                    ss[nj][1] += v1 * v1;
                    *(unsigned short*)(dst + (size_t)c * NN + n) = packh(v0);
                    *(unsigned short*)(dst + (size_t)(c + 1) * NN + n) = packh(v1);
                }
            }
        // reduce over the 8 lanes sharing each c column (lane>>2 varies)
        #pragma unroll
        for (int nj = 0; nj < 4; nj++)
            #pragma unroll
            for (int e = 0; e < 2; e++) {
                float s = ss[nj][e];
                s += __shfl_xor_sync(0xffffffffu, s, 4);
                s += __shfl_xor_sync(0xffffffffu, s, 8);
                s += __shfl_xor_sync(0xffffffffu, s, 16);
                ss[nj][e] = s;
            }
        if ((lane >> 2) == 0) {
            float* ssq = (which ? g_ssq_k : g_ssq_q) + b * DINNER;
            #pragma unroll
            for (int nj = 0; nj < 4; nj++) {
                atomicAdd(ssq + cbase + nj * 8,     ss[nj][0]);
                atomicAdd(ssq + cbase + nj * 8 + 1, ss[nj][1]);
            }
        }
    } else {
        #pragma unroll
        for (int mi = 0; mi < 4; mi++)
            #pragma unroll
            for (int h = 0; h < 2; h++) {
                int n = nbase + mi * 16 + h * 8;
                size_t base = ((size_t)b * NN + n) * DINNER + cbase;
                #pragma unroll
                for (int nj = 0; nj < 4; nj++)
                    *(uint32_t*)(g_v + base + nj * 8) =
                        packh2(acc[mi][nj][h * 2], acc[mi][nj][h * 2 + 1]);
            }
    }
}

// -------- K4: sim partials via HMMA over a 512-wide n slice ----
__global__ __launch_bounds__(256) void k_sim_mma() {
    extern __shared__ char smem[];
    const int bh = blockIdx.x;   // 64
    const int sp = blockIdx.y;   // 8 splits of n
    float acc[2][2][4];
    #pragma unroll
    for (int i = 0; i < 2; i++)
        #pragma unroll
        for (int j = 0; j < 2; j++)
            #pragma unroll
            for (int r = 0; r < 4; r++) acc[i][j][r] = 0.f;

    const size_t base = (size_t)bh * DHEAD * NN + sp * 512;
    mma_pipe<64, 2, 2, 8>(smem, g_q + base, g_k + base, NN, NN, acc);

    const int tid = threadIdx.x;
    const int wid = tid >> 5, lane = tid & 31;
    const int wm = wid >> 2, wn = wid & 3;
    float* gp = g_gpart + ((size_t)bh * 8 + sp) * 4096;
    #pragma unroll
    for (int mi = 0; mi < 2; mi++)
        #pragma unroll
        for (int h = 0; h < 2; h++) {
            int d = wm * 32 + mi * 16 + (lane >> 2) + h * 8;
            #pragma unroll
            for (int nj = 0; nj < 2; nj++) {
                int e = wn * 16 + nj * 8 + 2 * (lane & 3);
                *(float2*)(gp + d * 64 + e) =
                    make_float2(acc[mi][nj][h * 2], acc[mi][nj][h * 2 + 1]);
            }
        }
}

// -------- K5: reduce + scale (norms from fused sums) + softmax --------
__global__ void k_softmax(const float* __restrict__ temperature) {
    const int bh = blockIdx.x;
    const int d = threadIdx.x;
    const int hh = bh & 7;
    const float invq = 1.0f / fmaxf(sqrtf(g_ssq_q[bh * 64 + d]), 1e-12f);
    const float sc = 8.0f * expf(temperature[hh]) * invq;
    __shared__ float invk[64];
    invk[d] = 1.0f / fmaxf(sqrtf(g_ssq_k[bh * 64 + d]), 1e-12f);
    __syncthreads();
    const float* gp = g_gpart + (size_t)bh * 8 * 4096;
    float vals[64];
    float mx = -1e30f;
    #pragma unroll 4
    for (int e = 0; e < 64; e++) {
        float s = 0.f;
        #pragma unroll
        for (int sp = 0; sp < 8; sp++) s += gp[sp * 4096 + d * 64 + e];
        s *= sc * invk[e];
        vals[e] = s;
        mx = fmaxf(mx, s);
    }
    float sum = 0.f;
    #pragma unroll 4
    for (int e = 0; e < 64; e++) { vals[e] = expf(vals[e] - mx); sum += vals[e]; }
    const float inv = 1.0f / sum;
    #pragma unroll 4
    for (int e = 0; e < 64; e++)
        g_attn[(size_t)bh * 4096 + d * 64 + e] = vals[e] * inv;
}

// -------- K6: fold attn into w_out, write transposed fp16 [b][j][c] --------
__global__ __launch_bounds__(256) void k_attnw(const float* __restrict__ w_out) {
    const int bh = blockIdx.x;
    const int jt = blockIdx.y;
    const int b = bh >> 3, hh = bh & 7;
    __shared__ float As[64][64];
    const int tid = threadIdx.x;
    #pragma unroll
    for (int t = 0; t < 16; t++) {
        int idx = tid + 256 * t;
        As[idx >> 6][idx & 63] = g_attn[(size_t)bh * 4096 + idx];
    }
    __syncthreads();
    const int j = jt * 128 + (tid & 127);
    const int e0 = (tid >> 7) * 32;
    float acc[32];
    #pragma unroll
    for (int i = 0; i < 32; i++) acc[i] = 0.f;
    for (int d = 0; d < 64; d++) {
        float w = w_out[(hh * 64 + d) * DIM + j];
        #pragma unroll
        for (int i = 0; i < 32; i++) acc[i] += As[d][e0 + i] * w;
    }
    size_t base = ((size_t)b * 512 + j) * 512 + hh * 64 + e0;
    #pragma unroll
    for (int i = 0; i < 32; i++)
        g_aw[base + i] = __float2half_rn(acc[i]);
}

// -------- final GEMM: out[b][n][j] = sum_c V[b][n][c] * aw[b][j][c] --------
__global__ __launch_bounds__(256, 2) void k_final_mma(float* __restrict__ out) {
    extern __shared__ char smem[];
    const int m0 = blockIdx.x * 128;   // n
    const int j0 = blockIdx.y * 128;   // j
    const int b = blockIdx.z;
    float acc[4][4][4];
    #pragma unroll
    for (int i = 0; i < 4; i++)
        #pragma unroll
        for (int j = 0; j < 4; j++)
            #pragma unroll
            for (int r = 0; r < 4; r++) acc[i][j][r] = 0.f;

    mma_pipe<128, 4, 4, 8>(smem,
                 g_v + ((size_t)b * NN + m0) * 512,
                 g_aw + ((size_t)b * 512 + j0) * 512, 512, 512, acc);

    const int tid = threadIdx.x;
    const int wid = tid >> 5, lane = tid & 31;
    const int wm = wid >> 2, wn = wid & 3;
    const int nbase = m0 + wm * 64 + (lane >> 2);
    const int jbase = j0 + wn * 32 + 2 * (lane & 3);
    #pragma unroll
    for (int mi = 0; mi < 4; mi++)
        #pragma unroll
        for (int h = 0; h < 2; h++) {
            int n = nbase + mi * 16 + h * 8;
            float* orow = out + ((size_t)b * NN + n) * DIM + jbase;
            #pragma unroll
            for (int nj = 0; nj < 4; nj++) {
                float2 v = make_float2(acc[mi][nj][h * 2], acc[mi][nj][h * 2 + 1]);
                *(float2*)(orow + nj * 8) = v;
            }
        }
}

// -------- launch --------
extern "C" void kernel_launch(void* const* d_in, const int* in_sizes, int n_in,
                              void* d_out, int out_size) {
    const float* x           = (const float*)d_in[0];
    const float* gamma       = (const float*)d_in[1];
    const float* w_qkv       = (const float*)d_in[2];
    const float* temperature = (const float*)d_in[3];
    const float* w_out       = (const float*)d_in[4];
    float* out = (float*)d_out;

    static int attr_done = 0;
    if (!attr_done) {
        cudaFuncSetAttribute(k_qkv_mma, cudaFuncAttributeMaxDynamicSharedMemorySize, SMEM_GEMM);
        cudaFuncSetAttribute(k_final_mma, cudaFuncAttributeMaxDynamicSharedMemorySize, SMEM_GEMM);
        cudaFuncSetAttribute(k_sim_mma, cudaFuncAttributeMaxDynamicSharedMemorySize, SMEM_SIM);
        attr_done = 1;
    }

    k_zero     <<<16, 256>>>();
    k_prepA    <<<BB * NN, 128>>>(x, gamma);
    k_prepW    <<<dim3(48, 16), dim3(32, 8)>>>(w_qkv);
    k_qkv_mma  <<<dim3(256, 12), 256, SMEM_GEMM>>>();
    k_sim_mma  <<<dim3(BH, 8), 256, SMEM_SIM>>>();
    k_softmax  <<<BH, 64>>>(temperature);
    k_attnw    <<<dim3(BH, 4), 256>>>(w_out);
    k_final_mma<<<dim3(32, 4, BB), 256, SMEM_GEMM>>>(out);
}